// round 4
// baseline (speedup 1.0000x reference)
#include <cuda_runtime.h>

// ConvSepKanCell: per-pixel dynamic KAN — float4 (4 pixels/thread), 1 output/thread.
// x: (2, 16, 128, 128) f32   w: (2, 3328, 128, 128) f32   out: (2, 16, 128, 128) f32
// Param layout along dim-1 of w (per pixel):
//   [0, 2816)      coef[i][o][m]  (16 x 16 x 11)
//   [2816, 3072)   uw[i][o]
//   [3072, 3328)   rw[i][o]
// y[o] = sum_i uw[i][o] * (sum_m coef[i][o][m]*B3_m(x_i)) + rw[i][o]*silu(x_i)

#define HW      16384
#define HW4     4096      // float4 elements per plane
#define INC     16
#define OUTC    16
#define COEFM   11
#define SIZE_W  3328
#define I0      2816
#define I1      3072
#define OSPLIT  16        // 1 output per thread

__global__ __launch_bounds__(128)
void kan_kernel(const float* __restrict__ x,
                const float* __restrict__ w,
                float* __restrict__ out)
{
    const int t = blockIdx.x * 128 + threadIdx.x;   // 0..8191 (float4 slots, both batches)
    const int o = blockIdx.y;                       // output channel 0..15
    const int b   = t >> 12;
    const int hw4 = t & (HW4 - 1);

    const float4* wp = (const float4*)(w + (size_t)b * SIZE_W * HW) + hw4;
    const float4* xp = (const float4*)(x + (size_t)b * INC * HW) + hw4;

    const float4* cp = wp + (size_t)(o * COEFM) * HW4;
    const float4* up = wp + (size_t)(I0 + o) * HW4;
    const float4* rp = wp + (size_t)(I1 + o) * HW4;

    float ya = 0.f, yb = 0.f, yc = 0.f, yd = 0.f;

    for (int i = 0; i < INC; ++i) {
        const float4 xi = __ldg(xp);
        xp += HW4;

        // ---- Cox-de Boor, K=3, uniform knots grid[j] = 0.25j - 1.75 (exact fp32) ----
        float ba[14], bb[14], bc[14], bd[14];
        #pragma unroll
        for (int j = 0; j < 14; ++j) {
            const float gj = 0.25f * (float)j - 1.75f;
            const float gj1 = gj + 0.25f;
            ba[j] = (xi.x >= gj && xi.x < gj1) ? 1.f : 0.f;
            bb[j] = (xi.y >= gj && xi.y < gj1) ? 1.f : 0.f;
            bc[j] = (xi.z >= gj && xi.z < gj1) ? 1.f : 0.f;
            bd[j] = (xi.w >= gj && xi.w < gj1) ? 1.f : 0.f;
        }
        const float ta = fmaf(xi.x, 4.0f, 7.0f);
        const float tb = fmaf(xi.y, 4.0f, 7.0f);
        const float tc = fmaf(xi.z, 4.0f, 7.0f);
        const float td = fmaf(xi.w, 4.0f, 7.0f);
        #pragma unroll
        for (int p = 1; p <= 3; ++p) {
            const float invp = 1.0f / (float)p;
            #pragma unroll
            for (int j = 0; j < 14 - p; ++j) {
                const float fj = (float)j, fjp = (float)(j + p + 1);
                ba[j] = ((ta - fj) * invp) * ba[j] + ((fjp - ta) * invp) * ba[j + 1];
                bb[j] = ((tb - fj) * invp) * bb[j] + ((fjp - tb) * invp) * bb[j + 1];
                bc[j] = ((tc - fj) * invp) * bc[j] + ((fjp - tc) * invp) * bc[j + 1];
                bd[j] = ((td - fj) * invp) * bd[j] + ((fjp - td) * invp) * bd[j + 1];
            }
        }
        const float sxa = xi.x / (1.0f + __expf(-xi.x));
        const float sxb = xi.y / (1.0f + __expf(-xi.y));
        const float sxc = xi.z / (1.0f + __expf(-xi.z));
        const float sxd = xi.w / (1.0f + __expf(-xi.w));

        // ---- spline contraction for 1 output x 4 pixels ----
        float sa = 0.f, sb = 0.f, sc = 0.f, sd = 0.f;
        #pragma unroll
        for (int m = 0; m < COEFM; ++m) {
            const float4 c = __ldcs(cp + m * HW4);
            sa = fmaf(c.x, ba[m], sa);
            sb = fmaf(c.y, bb[m], sb);
            sc = fmaf(c.z, bc[m], sc);
            sd = fmaf(c.w, bd[m], sd);
        }
        const float4 u = __ldcs(up);
        const float4 r = __ldcs(rp);
        ya += u.x * sa + r.x * sxa;
        yb += u.y * sb + r.y * sxb;
        yc += u.z * sc + r.z * sxc;
        yd += u.w * sd + r.w * sxd;

        cp += (size_t)(OUTC * COEFM) * HW4;
        up += (size_t)OUTC * HW4;
        rp += (size_t)OUTC * HW4;
    }

    float4* op = (float4*)(out + (size_t)b * OUTC * HW) + (size_t)o * HW4 + hw4;
    *op = make_float4(ya, yb, yc, yd);
}

extern "C" void kernel_launch(void* const* d_in, const int* in_sizes, int n_in,
                              void* d_out, int out_size)
{
    const float* x = (const float*)d_in[0];
    const float* w = (const float*)d_in[1];
    float* out = (float*)d_out;

    dim3 grid(8192 / 128, OSPLIT);   // (64, 16) = 1024 blocks of 128 threads
    kan_kernel<<<grid, 128>>>(x, w, out);
}

// round 5
// speedup vs baseline: 1.5572x; 1.5572x over previous
#include <cuda_runtime.h>

// ConvSepKanCell: per-pixel dynamic KAN — float2 (2 pixels/thread), 2 outputs/thread.
// x: (2, 16, 128, 128) f32   w: (2, 3328, 128, 128) f32   out: (2, 16, 128, 128) f32
// Param layout along dim-1 of w (per pixel):
//   [0, 2816)      coef[i][o][m]  (16 x 16 x 11)
//   [2816, 3072)   uw[i][o]
//   [3072, 3328)   rw[i][o]
// y[o] = sum_i uw[i][o] * (sum_m coef[i][o][m]*B3_m(x_i)) + rw[i][o]*silu(x_i)

#define HW      16384
#define HW2     8192      // float2 elements per image plane
#define INC     16
#define OUTC    16
#define COEFM   11
#define SIZE_W  3328
#define I0      2816
#define I1      3072
#define OSPLIT  8         // outputs per thread = 2
#define TPB     128

__device__ __forceinline__ float2 ldcs2(const float2* p) { return __ldcs(p); }

__global__ __launch_bounds__(TPB, 8)
void kan_kernel(const float* __restrict__ x,
                const float* __restrict__ w,
                float* __restrict__ out)
{
    const int t     = blockIdx.x * TPB + threadIdx.x;   // 0..16383 (float2 slots)
    const int slice = blockIdx.y;                       // 0..7 -> outputs slice*2..+2
    const int b   = t >> 13;
    const int hw2 = t & (HW2 - 1);

    const float2* wp = (const float2*)(w + (size_t)b * SIZE_W * HW) + hw2;
    const float2* xp = (const float2*)(x + (size_t)b * INC * HW) + hw2;

    const float2* cp = wp + (size_t)(slice * 2 * COEFM) * HW2;
    const float2* up = wp + (size_t)(I0 + slice * 2) * HW2;
    const float2* rp = wp + (size_t)(I1 + slice * 2) * HW2;

    float y0a = 0.f, y0b = 0.f, y1a = 0.f, y1b = 0.f;

    for (int i = 0; i < INC; ++i) {
        const float2 xi = __ldg(xp);
        xp += HW2;

        // ---- Cox-de Boor, K=3, uniform knots grid[j] = 0.25j - 1.75 (exact fp32) ----
        float ba[14], bc[14];
        #pragma unroll
        for (int j = 0; j < 14; ++j) {
            const float gj = 0.25f * (float)j - 1.75f;
            ba[j] = (xi.x >= gj && xi.x < gj + 0.25f) ? 1.f : 0.f;
            bc[j] = (xi.y >= gj && xi.y < gj + 0.25f) ? 1.f : 0.f;
        }
        const float ta = fmaf(xi.x, 4.0f, 7.0f);
        const float tc = fmaf(xi.y, 4.0f, 7.0f);
        #pragma unroll
        for (int p = 1; p <= 3; ++p) {
            const float invp = 1.0f / (float)p;
            #pragma unroll
            for (int j = 0; j < 14 - p; ++j) {
                const float la = (ta - (float)j) * invp;
                const float ra = ((float)(j + p + 1) - ta) * invp;
                ba[j] = la * ba[j] + ra * ba[j + 1];
                const float lc = (tc - (float)j) * invp;
                const float rc = ((float)(j + p + 1) - tc) * invp;
                bc[j] = lc * bc[j] + rc * bc[j + 1];
            }
        }
        const float sxa = xi.x / (1.0f + __expf(-xi.x));
        const float sxb = xi.y / (1.0f + __expf(-xi.y));

        // ---- spline contraction for 2 outputs x 2 pixels ----
        float s0a = 0.f, s0b = 0.f, s1a = 0.f, s1b = 0.f;
        #pragma unroll
        for (int m = 0; m < COEFM; ++m) {
            const float2 c0 = ldcs2(cp + (0 * COEFM + m) * HW2);
            const float2 c1 = ldcs2(cp + (1 * COEFM + m) * HW2);
            s0a = fmaf(c0.x, ba[m], s0a);
            s0b = fmaf(c0.y, bc[m], s0b);
            s1a = fmaf(c1.x, ba[m], s1a);
            s1b = fmaf(c1.y, bc[m], s1b);
        }
        const float2 u0 = ldcs2(up + 0 * HW2);
        const float2 u1 = ldcs2(up + 1 * HW2);
        const float2 r0 = ldcs2(rp + 0 * HW2);
        const float2 r1 = ldcs2(rp + 1 * HW2);
        y0a += u0.x * s0a + r0.x * sxa;
        y0b += u0.y * s0b + r0.y * sxb;
        y1a += u1.x * s1a + r1.x * sxa;
        y1b += u1.y * s1b + r1.y * sxb;

        cp += (size_t)(OUTC * COEFM) * HW2;
        up += (size_t)OUTC * HW2;
        rp += (size_t)OUTC * HW2;
    }

    float2* op = (float2*)(out + (size_t)b * OUTC * HW) + (size_t)(slice * 2) * HW2 + hw2;
    op[0 * HW2] = make_float2(y0a, y0b);
    op[1 * HW2] = make_float2(y1a, y1b);
}

extern "C" void kernel_launch(void* const* d_in, const int* in_sizes, int n_in,
                              void* d_out, int out_size)
{
    const float* x = (const float*)d_in[0];
    const float* w = (const float*)d_in[1];
    float* out = (float*)d_out;

    dim3 grid(16384 / TPB, OSPLIT);   // (128, 8) = 1024 blocks of 128 threads
    kan_kernel<<<grid, TPB>>>(x, w, out);
}